// round 10
// baseline (speedup 1.0000x reference)
#include <cuda_runtime.h>
#include <cuda_fp16.h>
#include <math.h>

#define SEQ 4096
#define HDIM 1024
#define NH 16
#define HD 64
#define WSTR 36    // words per 64-half row (attention tiles)
#define ASTR 20    // words per 32-half row (GEMM tiles)

// ---------------- device scratch ----------------
__device__ __half g_Qh[NH * SEQ * HD];    // [h][s][d], pre-scaled by 0.125*log2(e)
__device__ __half g_Kh[NH * SEQ * HD];    // [h][s][d]
__device__ __half g_Vh[NH * SEQ * HD];    // [h][d][s]  TRANSPOSED
__device__ __half g_ctxh[SEQ * HDIM];
__device__ __half g_xh[SEQ * HDIM];
__device__ __half g_Wqh[HDIM * HDIM];     // transposed [n][k]
__device__ __half g_Wkh[HDIM * HDIM];
__device__ __half g_Wvh[HDIM * HDIM];
__device__ __half g_Woh[HDIM * HDIM];
__device__ float g_cos[SEQ * HD];
__device__ float g_sin[SEQ * HD];

// ---------------- helpers ----------------
__device__ __forceinline__ void mma16(float* c, const unsigned* a, const unsigned* b) {
    asm volatile(
        "mma.sync.aligned.m16n8k16.row.col.f32.f16.f16.f32 "
        "{%0,%1,%2,%3}, {%4,%5,%6,%7}, {%8,%9}, {%0,%1,%2,%3};\n"
        : "+f"(c[0]), "+f"(c[1]), "+f"(c[2]), "+f"(c[3])
        : "r"(a[0]), "r"(a[1]), "r"(a[2]), "r"(a[3]), "r"(b[0]), "r"(b[1]));
}

__device__ __forceinline__ void ldm_x4(unsigned* r, unsigned addr) {
    asm volatile("ldmatrix.sync.aligned.m8n8.x4.shared.b16 {%0,%1,%2,%3}, [%4];"
                 : "=r"(r[0]), "=r"(r[1]), "=r"(r[2]), "=r"(r[3]) : "r"(addr));
}

__device__ __forceinline__ unsigned packh2(float lo, float hi) {
    __half2 h = __floats2half2_rn(lo, hi);
    return *(unsigned*)&h;
}

__device__ __forceinline__ void cp16(unsigned dst, const void* src) {
    asm volatile("cp.async.cg.shared.global [%0], [%1], 16;" :: "r"(dst), "l"(src));
}
__device__ __forceinline__ void cp4(unsigned dst, const void* src) {
    asm volatile("cp.async.ca.shared.global [%0], [%1], 4;" :: "r"(dst), "l"(src));
}
#define CP_COMMIT() asm volatile("cp.async.commit_group;")

// ---------------- prep kernels ----------------
__global__ void x2h_kernel(const float* __restrict__ x) {
    int i = blockIdx.x * 256 + threadIdx.x;
    float4 v = ((const float4*)x)[i];
    uint2 u;
    u.x = packh2(v.x, v.y);
    u.y = packh2(v.z, v.w);
    ((uint2*)g_xh)[i] = u;
}

__global__ void wtrans_kernel(const float* __restrict__ Wq,
                              const float* __restrict__ Wk,
                              const float* __restrict__ Wv,
                              const float* __restrict__ Wo) {
    __shared__ float tile[64][65];
    const int z = blockIdx.z;
    const float* W = (z == 0) ? Wq : (z == 1) ? Wk : (z == 2) ? Wv : Wo;
    __half* Wt = (z == 0) ? g_Wqh : (z == 1) ? g_Wkh : (z == 2) ? g_Wvh : g_Woh;
    const int k0 = blockIdx.x * 64, n0 = blockIdx.y * 64;
    const int tid = threadIdx.x;
#pragma unroll
    for (int i = 0; i < 16; i++) {
        int idx = tid + 256 * i;
        int r = idx >> 6, c = idx & 63;
        tile[r][c] = W[(size_t)(k0 + r) * HDIM + n0 + c];
    }
    __syncthreads();
#pragma unroll
    for (int i = 0; i < 16; i++) {
        int idx = tid + 256 * i;
        int r = idx >> 6, c = idx & 63;
        Wt[(size_t)(n0 + r) * HDIM + k0 + c] = __float2half_rn(tile[c][r]);
    }
}

// ---------------- RoPE tables ----------------
__global__ void rope_tables_kernel() {
    int idx = blockIdx.x * 256 + threadIdx.x;
    if (idx >= SEQ * HD) return;
    int t = idx >> 6;
    int j = idx & 63;
    int i = j & 31;
    float xe = (float)(2 * i) / 64.0f;
    float pf = (float)pow(10000.0, (double)xe);
    float invf = 1.0f / pf;
    float angf = (float)t * invf;
    double ang = (double)angf;
    g_cos[idx] = (float)cos(ang);
    g_sin[idx] = (float)sin(ang);
}

// ---------------- fp16 GEMM core: C[128x128], 3-stage ring, 1 sync/iter ----------------
// 8 warps = 4M x 2N, warp tile m32 x n64, k-step 32.
#define NSTAGE 3
#define GEMM_NI (HDIM / 32)
#define GEMM_SMEM (NSTAGE * (128 + 128) * ASTR * 4)

__device__ __forceinline__ void gemm_core_128x128(
    const __half* __restrict__ A, const __half* __restrict__ Wt,
    int s0, int n0, float acc[2][8][4], unsigned* smem)
{
    const int tid = threadIdx.x;
    const int lane = tid & 31;
    const int warp = tid >> 5;
    const int wm = warp & 3;
    const int wn = warp >> 2;
    const int qb = wm * 32;

    unsigned asb = (unsigned)__cvta_generic_to_shared(smem);
    unsigned bsb = asb + (unsigned)(NSTAGE * 128 * ASTR) * 4u;

    const int arow = lane & 15;
    const int acolw = (lane >> 4) * 4;
    const int brow = ((lane & 16) ? 8 : 0) + (lane & 7);
    const int bcolw = ((lane >> 3) & 1) * 4;

    auto issue = [&](int i) {
        int k0 = i * 32;
        unsigned slot = (unsigned)(i % NSTAGE);
#pragma unroll
        for (int r = 0; r < 2; r++) {           // A: 128 rows x 4 chunks
            int f = tid + 256 * r;
            int row = f >> 2, ch = f & 3;
            cp16(asb + (slot * 128 * ASTR + row * ASTR + ch * 4) * 4u,
                 &A[(size_t)(s0 + row) * HDIM + k0 + ch * 8]);
        }
#pragma unroll
        for (int r = 0; r < 2; r++) {           // B: 128 rows x 4 chunks
            int f = tid + 256 * r;
            int row = f >> 2, ch = f & 3;
            cp16(bsb + (slot * 128 * ASTR + row * ASTR + ch * 4) * 4u,
                 &Wt[(size_t)(n0 + row) * HDIM + k0 + ch * 8]);
        }
        CP_COMMIT();
    };

    issue(0);
    issue(1);

    for (int i = 0; i < GEMM_NI; i++) {
        if (i == GEMM_NI - 1) {
            asm volatile("cp.async.wait_group 0;");
        } else {
            asm volatile("cp.async.wait_group 1;");
        }
        __syncthreads();
        if (i + 2 < GEMM_NI) issue(i + 2);

        unsigned slot = (unsigned)(i % NSTAGE);
        unsigned a_base0 = asb + (slot * 128 * ASTR + (qb + arow) * ASTR + acolw) * 4u;
        unsigned a_base1 = a_base0 + (unsigned)(16 * ASTR) * 4u;
        unsigned b_base = bsb + (slot * 128 * ASTR + (wn * 64 + brow) * ASTR + bcolw) * 4u;

#pragma unroll
        for (int kg = 0; kg < 2; kg++) {
            unsigned a0[4], a1[4];
            ldm_x4(a0, a_base0 + kg * 32u);
            ldm_x4(a1, a_base1 + kg * 32u);
#pragma unroll
            for (int nb = 0; nb < 4; nb++) {
                unsigned b[4];
                ldm_x4(b, b_base + (unsigned)(nb * 16 * ASTR) * 4u + kg * 32u);
                mma16(acc[0][2 * nb], a0, b);
                mma16(acc[0][2 * nb + 1], a0, b + 2);
                mma16(acc[1][2 * nb], a1, b);
                mma16(acc[1][2 * nb + 1], a1, b + 2);
            }
        }
    }
}

// ---------------- QKV projection + RoPE ----------------
#define LOG2E 1.44269504088896340736f

__global__ void __launch_bounds__(256) qkv_kernel() {
    extern __shared__ unsigned gsm[];

    const int z = blockIdx.z;
    const __half* Wt = (z == 0) ? g_Wqh : ((z == 1) ? g_Wkh : g_Wvh);

    const int tid = threadIdx.x;
    const int lane = tid & 31;
    const int warp = tid >> 5;
    const int wm = warp & 3;
    const int wn = warp >> 2;
    const int gid = lane >> 2;
    const int tig = lane & 3;
    const int s0 = blockIdx.y * 128;
    const int n0 = blockIdx.x * 128;
    const float qscale = (z == 0) ? 0.125f * LOG2E : 1.0f;

    float acc[2][8][4] = {};
    gemm_core_128x128(g_xh, Wt, s0, n0, acc, gsm);

    const int head = blockIdx.x * 2 + wn;   // each warp-column = one head (64 cols)
#pragma unroll
    for (int ma = 0; ma < 2; ma++) {
#pragma unroll
        for (int nf = 0; nf < 8; nf++) {
#pragma unroll
            for (int rr = 0; rr < 2; rr++) {
                int row = s0 + wm * 32 + ma * 16 + gid + rr * 8;
                int d = nf * 8 + 2 * tig;   // within-head dim (nf covers 0..63)
                float v0 = acc[ma][nf][2 * rr + 0];
                float v1 = acc[ma][nf][2 * rr + 1];
                if (z < 2) {
                    float2 c = *(const float2*)&g_cos[row * HD + d];
                    float2 s = *(const float2*)&g_sin[row * HD + d];
                    float o0 = (v0 * c.x - v1 * s.x) * qscale;
                    float o1 = (v1 * c.y + v0 * s.y) * qscale;
                    __half* dst = (z == 0) ? g_Qh : g_Kh;
                    *(unsigned*)&dst[(size_t)head * SEQ * HD + (size_t)row * HD + d] =
                        packh2(o0, o1);
                } else {
                    size_t base = (size_t)head * SEQ * HD;
                    g_Vh[base + (size_t)d * SEQ + row] = __float2half_rn(v0);
                    g_Vh[base + (size_t)(d + 1) * SEQ + row] = __float2half_rn(v1);
                }
            }
        }
    }
}

// ---------------- output projection ----------------
__global__ void __launch_bounds__(256) oproj_kernel(float* __restrict__ out) {
    extern __shared__ unsigned gsm[];

    const int tid = threadIdx.x;
    const int lane = tid & 31;
    const int warp = tid >> 5;
    const int wm = warp & 3;
    const int wn = warp >> 2;
    const int gid = lane >> 2;
    const int tig = lane & 3;
    const int s0 = blockIdx.y * 128;
    const int n0 = blockIdx.x * 128;

    float acc[2][8][4] = {};
    gemm_core_128x128(g_ctxh, g_Woh, s0, n0, acc, gsm);

#pragma unroll
    for (int ma = 0; ma < 2; ma++)
#pragma unroll
        for (int nf = 0; nf < 8; nf++)
#pragma unroll
            for (int rr = 0; rr < 2; rr++) {
                int row = s0 + wm * 32 + ma * 16 + gid + rr * 8;
                int col = n0 + wn * 64 + nf * 8 + 2 * tig;
                *(float2*)&out[(size_t)row * HDIM + col] =
                    make_float2(acc[ma][nf][2 * rr + 0], acc[ma][nf][2 * rr + 1]);
            }
}

// ---------------- flash attention: 3-stage ring, 1 sync/tile ----------------
#define ATT_NI (SEQ / 64)
#define ATT_SMEM ((128 * WSTR + 3 * 64 * WSTR + 3 * 64 * WSTR) * 4 + 3 * 64 * 4)

__global__ void __launch_bounds__(256, 2) attn_kernel(const int* __restrict__ mask) {
    extern __shared__ unsigned sm_u[];
    unsigned* Qs = sm_u;                              // 128 x WSTR
    unsigned* Ks = Qs + 128 * WSTR;                   // 3 x 64 x WSTR
    unsigned* Vs = Ks + 3 * 64 * WSTR;                // 3 x 64 x WSTR
    int* smask = (int*)(Vs + 3 * 64 * WSTR);          // 3 x 64

    const int tid = threadIdx.x;
    const int lane = tid & 31;
    const int w = tid >> 5;
    const int gid = lane >> 2;
    const int tig = lane & 3;
    const int q0 = blockIdx.x * 128;
    const int h = blockIdx.y;
    const int qb = w * 16;

    const __half* Qg = g_Qh + (size_t)h * SEQ * HD;
    const __half* Kg = g_Kh + (size_t)h * SEQ * HD;
    const __half* Vg = g_Vh + (size_t)h * SEQ * HD;   // [d][s]

    unsigned qsb = (unsigned)__cvta_generic_to_shared(Qs);
    unsigned ksb = (unsigned)__cvta_generic_to_shared(Ks);
    unsigned vsb = (unsigned)__cvta_generic_to_shared(Vs);
    unsigned msb = (unsigned)__cvta_generic_to_shared(smask);

    const int arow = lane & 15;
    const int acolw = (lane >> 4) * 4;
    const int brow = ((lane & 16) ? 8 : 0) + (lane & 7);
    const int bcolw = ((lane >> 3) & 1) * 4;

    auto issue_kv = [&](int kt) {
        int k0 = kt * 64;
        unsigned slot = (unsigned)(kt % 3);
#pragma unroll
        for (int i = 0; i < 2; i++) {
            int f = tid + 256 * i;
            int row = f >> 3, ch = f & 7;
            cp16(ksb + (slot * 64 * WSTR + row * WSTR + ch * 4) * 4u,
                 &Kg[(size_t)(k0 + row) * HD + ch * 8]);
            cp16(vsb + (slot * 64 * WSTR + row * WSTR + ch * 4) * 4u,
                 &Vg[(size_t)row * SEQ + k0 + ch * 8]);
        }
        if (tid < 64) cp4(msb + (slot * 64 + tid) * 4u, &mask[k0 + tid]);
        CP_COMMIT();
    };

    // stage Q once
#pragma unroll
    for (int i = 0; i < 4; i++) {
        int f = tid + 256 * i;
        int row = f >> 3, ch = f & 7;
        *(uint4*)&Qs[row * WSTR + ch * 4] =
            *(const uint4*)&Qg[(size_t)(q0 + row) * HD + ch * 8];
    }

    float Oacc[8][4] = {};
    float mrow[2] = {-1e30f, -1e30f};
    float lrow[2] = {0.f, 0.f};

    issue_kv(0);
    issue_kv(1);

    const unsigned qaddr = qsb + (unsigned)((qb + arow) * WSTR + acolw) * 4u;

    for (int kt = 0; kt < ATT_NI; kt++) {
        if (kt == ATT_NI - 1) {
            asm volatile("cp.async.wait_group 0;");
        } else {
            asm volatile("cp.async.wait_group 1;");
        }
        __syncthreads();
        if (kt + 2 < ATT_NI) issue_kv(kt + 2);

        unsigned slot = (unsigned)(kt % 3);
        const unsigned kbase = ksb + (slot * 64 * WSTR + brow * WSTR + bcolw) * 4u;
        const unsigned vbase = vsb + (slot * 64 * WSTR + brow * WSTR + bcolw) * 4u;
        const int* Mf = smask + slot * 64;

        // ---- S = Q K^T ----
        float sacc[8][4] = {};
#pragma unroll
        for (int kg = 0; kg < 4; kg++) {
            unsigned a[4];
            ldm_x4(a, qaddr + kg * 32u);
#pragma unroll
            for (int nb = 0; nb < 4; nb++) {
                unsigned b[4];
                ldm_x4(b, kbase + (unsigned)(nb * 16 * WSTR) * 4u + kg * 32u);
                mma16(sacc[2 * nb], a, b);
                mma16(sacc[2 * nb + 1], a, b + 2);
            }
        }

        // ---- mask bias (skip when tile all-ones) ----
        bool localz = false;
        float bb[8][2];
#pragma unroll
        for (int na = 0; na < 8; na++) {
            int m0 = Mf[na * 8 + 2 * tig];
            int m1 = Mf[na * 8 + 2 * tig + 1];
            bb[na][0] = (m0 == 0) ? -1e30f : 0.f;
            bb[na][1] = (m1 == 0) ? -1e30f : 0.f;
            localz |= (m0 == 0) | (m1 == 0);
        }
        if (__any_sync(0xffffffffu, localz)) {
#pragma unroll
            for (int na = 0; na < 8; na++)
#pragma unroll
                for (int rr = 0; rr < 2; rr++) {
                    sacc[na][2 * rr + 0] += bb[na][0];
                    sacc[na][2 * rr + 1] += bb[na][1];
                }
        }

        // ---- online softmax (exp2 domain; S pre-scaled by log2e) ----
#pragma unroll
        for (int rr = 0; rr < 2; rr++) {
            float mt = -1e30f;
#pragma unroll
            for (int na = 0; na < 8; na++)
                mt = fmaxf(mt, fmaxf(sacc[na][2 * rr], sacc[na][2 * rr + 1]));
            mt = fmaxf(mt, __shfl_xor_sync(0xffffffffu, mt, 1));
            mt = fmaxf(mt, __shfl_xor_sync(0xffffffffu, mt, 2));
            float mnew = fmaxf(mrow[rr], mt);
            float corr = exp2f(mrow[rr] - mnew);
            float rs = 0.f;
#pragma unroll
            for (int na = 0; na < 8; na++) {
#pragma unroll
                for (int s = 0; s < 2; s++) {
                    float p = exp2f(sacc[na][2 * rr + s] - mnew);
                    sacc[na][2 * rr + s] = p;
                    rs += p;
                }
            }
            rs += __shfl_xor_sync(0xffffffffu, rs, 1);
            rs += __shfl_xor_sync(0xffffffffu, rs, 2);
            lrow[rr] = lrow[rr] * corr + rs;
            mrow[rr] = mnew;
#pragma unroll
            for (int nd = 0; nd < 8; nd++) {
                Oacc[nd][2 * rr + 0] *= corr;
                Oacc[nd][2 * rr + 1] *= corr;
            }
        }

        // ---- O += P V ----
#pragma unroll
        for (int kg = 0; kg < 4; kg++) {
            unsigned aP[4];
            aP[0] = packh2(sacc[2 * kg][0], sacc[2 * kg][1]);
            aP[1] = packh2(sacc[2 * kg][2], sacc[2 * kg][3]);
            aP[2] = packh2(sacc[2 * kg + 1][0], sacc[2 * kg + 1][1]);
            aP[3] = packh2(sacc[2 * kg + 1][2], sacc[2 * kg + 1][3]);
#pragma unroll
            for (int nb = 0; nb < 4; nb++) {
                unsigned b[4];
                ldm_x4(b, vbase + (unsigned)(nb * 16 * WSTR) * 4u + kg * 32u);
                mma16(Oacc[2 * nb], aP, b);
                mma16(Oacc[2 * nb + 1], aP, b + 2);
            }
        }
    }

    // epilogue: normalize, write ctx fp16
    float inv[2] = {1.0f / lrow[0], 1.0f / lrow[1]};
#pragma unroll
    for (int nd = 0; nd < 8; nd++)
#pragma unroll
        for (int rr = 0; rr < 2; rr++) {
            int row = q0 + qb + gid + rr * 8;
            int d = nd * 8 + 2 * tig;
            float iv = inv[rr];
            *(unsigned*)&g_ctxh[(size_t)row * HDIM + h * HD + d] =
                packh2(Oacc[nd][2 * rr] * iv, Oacc[nd][2 * rr + 1] * iv);
        }
}

// ---------------- launch ----------------
extern "C" void kernel_launch(void* const* d_in, const int* in_sizes, int n_in,
                              void* d_out, int out_size) {
    const float* x  = (const float*)d_in[0];
    const float* Wq = (const float*)d_in[1];
    const float* Wk = (const float*)d_in[2];
    const float* Wv = (const float*)d_in[3];
    const float* Wo = (const float*)d_in[4];
    const int* mask = (const int*)d_in[5];
    float* out = (float*)d_out;

    cudaFuncSetAttribute(qkv_kernel,
                         cudaFuncAttributeMaxDynamicSharedMemorySize, GEMM_SMEM);
    cudaFuncSetAttribute(oproj_kernel,
                         cudaFuncAttributeMaxDynamicSharedMemorySize, GEMM_SMEM);
    cudaFuncSetAttribute(attn_kernel,
                         cudaFuncAttributeMaxDynamicSharedMemorySize, ATT_SMEM);

    x2h_kernel<<<SEQ * HDIM / 4 / 256, 256>>>(x);
    wtrans_kernel<<<dim3(HDIM / 64, HDIM / 64, 4), 256>>>(Wq, Wk, Wv, Wo);
    rope_tables_kernel<<<(SEQ * HD + 255) / 256, 256>>>();
    qkv_kernel<<<dim3(HDIM / 128, SEQ / 128, 3), 256, GEMM_SMEM>>>();
    attn_kernel<<<dim3(SEQ / 128, NH), 256, ATT_SMEM>>>(mask);
    oproj_kernel<<<dim3(HDIM / 128, SEQ / 128), 256, GEMM_SMEM>>>(out);
}

// round 12
// speedup vs baseline: 1.0302x; 1.0302x over previous
#include <cuda_runtime.h>
#include <cuda_fp16.h>
#include <math.h>

#define SEQ 4096
#define HDIM 1024
#define NH 16
#define HD 64
#define WSTR 36    // words per 64-half row (attention tiles)
#define ASTR 20    // words per 32-half row (GEMM tiles)

// ---------------- device scratch ----------------
__device__ __half g_Qh[NH * SEQ * HD];    // [h][s][d], pre-scaled by 0.125*log2(e)
__device__ __half g_Kh[NH * SEQ * HD];    // [h][s][d]
__device__ __half g_Vh[NH * SEQ * HD];    // [h][d][s]  TRANSPOSED
__device__ __half g_ctxh[SEQ * HDIM];
__device__ __half g_xh[SEQ * HDIM];
__device__ __half g_Wqh[HDIM * HDIM];     // transposed [n][k]
__device__ __half g_Wkh[HDIM * HDIM];
__device__ __half g_Wvh[HDIM * HDIM];
__device__ __half g_Woh[HDIM * HDIM];
__device__ float g_cos[SEQ * HD];
__device__ float g_sin[SEQ * HD];

// ---------------- helpers ----------------
__device__ __forceinline__ void mma16(float* c, const unsigned* a, const unsigned* b) {
    asm volatile(
        "mma.sync.aligned.m16n8k16.row.col.f32.f16.f16.f32 "
        "{%0,%1,%2,%3}, {%4,%5,%6,%7}, {%8,%9}, {%0,%1,%2,%3};\n"
        : "+f"(c[0]), "+f"(c[1]), "+f"(c[2]), "+f"(c[3])
        : "r"(a[0]), "r"(a[1]), "r"(a[2]), "r"(a[3]), "r"(b[0]), "r"(b[1]));
}

__device__ __forceinline__ void ldm_x4(unsigned* r, unsigned addr) {
    asm volatile("ldmatrix.sync.aligned.m8n8.x4.shared.b16 {%0,%1,%2,%3}, [%4];"
                 : "=r"(r[0]), "=r"(r[1]), "=r"(r[2]), "=r"(r[3]) : "r"(addr));
}

__device__ __forceinline__ unsigned packh2(float lo, float hi) {
    __half2 h = __floats2half2_rn(lo, hi);
    return *(unsigned*)&h;
}

__device__ __forceinline__ void cp16(unsigned dst, const void* src) {
    asm volatile("cp.async.cg.shared.global [%0], [%1], 16;" :: "r"(dst), "l"(src));
}
__device__ __forceinline__ void cp4(unsigned dst, const void* src) {
    asm volatile("cp.async.ca.shared.global [%0], [%1], 4;" :: "r"(dst), "l"(src));
}
#define CP_COMMIT() asm volatile("cp.async.commit_group;")

// ---------------- prep kernels ----------------
__global__ void x2h_kernel(const float* __restrict__ x) {
    int i = blockIdx.x * 256 + threadIdx.x;
    float4 v = ((const float4*)x)[i];
    uint2 u;
    u.x = packh2(v.x, v.y);
    u.y = packh2(v.z, v.w);
    ((uint2*)g_xh)[i] = u;
}

__global__ void wtrans_kernel(const float* __restrict__ Wq,
                              const float* __restrict__ Wk,
                              const float* __restrict__ Wv,
                              const float* __restrict__ Wo) {
    __shared__ float tile[64][65];
    const int z = blockIdx.z;
    const float* W = (z == 0) ? Wq : (z == 1) ? Wk : (z == 2) ? Wv : Wo;
    __half* Wt = (z == 0) ? g_Wqh : (z == 1) ? g_Wkh : (z == 2) ? g_Wvh : g_Woh;
    const int k0 = blockIdx.x * 64, n0 = blockIdx.y * 64;
    const int tid = threadIdx.x;
#pragma unroll
    for (int i = 0; i < 16; i++) {
        int idx = tid + 256 * i;
        int r = idx >> 6, c = idx & 63;
        tile[r][c] = W[(size_t)(k0 + r) * HDIM + n0 + c];
    }
    __syncthreads();
#pragma unroll
    for (int i = 0; i < 16; i++) {
        int idx = tid + 256 * i;
        int r = idx >> 6, c = idx & 63;
        Wt[(size_t)(n0 + r) * HDIM + k0 + c] = __float2half_rn(tile[c][r]);
    }
}

// ---------------- RoPE tables ----------------
__global__ void rope_tables_kernel() {
    int idx = blockIdx.x * 256 + threadIdx.x;
    if (idx >= SEQ * HD) return;
    int t = idx >> 6;
    int j = idx & 63;
    int i = j & 31;
    float xe = (float)(2 * i) / 64.0f;
    float pf = (float)pow(10000.0, (double)xe);
    float invf = 1.0f / pf;
    float angf = (float)t * invf;
    double ang = (double)angf;
    g_cos[idx] = (float)cos(ang);
    g_sin[idx] = (float)sin(ang);
}

// ---------------- fp16 GEMM core: C[128x64], 3-stage ring, k-step 32, 1 sync/iter ----------------
// 8 warps = 4M x 2N, warp tile m32 x n32.
#define NSTAGE 3
#define GEMM_NI (HDIM / 32)
#define GEMM_SMEM (NSTAGE * (128 + 64) * ASTR * 4)

__device__ __forceinline__ void gemm_core_128x64(
    const __half* __restrict__ A, const __half* __restrict__ Wt,
    int s0, int n0, float acc[2][4][4], unsigned* smem)
{
    const int tid = threadIdx.x;
    const int lane = tid & 31;
    const int warp = tid >> 5;
    const int wm = warp & 3;
    const int wn = warp >> 2;
    const int qb = wm * 32;

    unsigned asb = (unsigned)__cvta_generic_to_shared(smem);
    unsigned bsb = asb + (unsigned)(NSTAGE * 128 * ASTR) * 4u;

    const int arow = lane & 15;
    const int acolw = (lane >> 4) * 4;
    const int brow = ((lane & 16) ? 8 : 0) + (lane & 7);
    const int bcolw = ((lane >> 3) & 1) * 4;

    auto issue = [&](int i) {
        int k0 = i * 32;
        unsigned slot = (unsigned)(i % NSTAGE);
        // A: 128 rows x 4 chunks of 8 halves = 512 cp16 (2 per thread)
#pragma unroll
        for (int r = 0; r < 2; r++) {
            int f = tid + 256 * r;
            int row = f >> 2, ch = f & 3;
            cp16(asb + (slot * 128 * ASTR + row * ASTR + ch * 4) * 4u,
                 &A[(size_t)(s0 + row) * HDIM + k0 + ch * 8]);
        }
        // B: 64 rows x 4 chunks = 256 cp16 (1 per thread)
        {
            int row = tid >> 2, ch = tid & 3;
            cp16(bsb + (slot * 64 * ASTR + row * ASTR + ch * 4) * 4u,
                 &Wt[(size_t)(n0 + row) * HDIM + k0 + ch * 8]);
        }
        CP_COMMIT();
    };

    issue(0);
    issue(1);

    for (int i = 0; i < GEMM_NI; i++) {
        if (i == GEMM_NI - 1) {
            asm volatile("cp.async.wait_group 0;");
        } else {
            asm volatile("cp.async.wait_group 1;");
        }
        __syncthreads();
        if (i + 2 < GEMM_NI) issue(i + 2);

        unsigned slot = (unsigned)(i % NSTAGE);
        unsigned a_base0 = asb + (slot * 128 * ASTR + (qb + arow) * ASTR + acolw) * 4u;
        unsigned a_base1 = a_base0 + (unsigned)(16 * ASTR) * 4u;
        unsigned b_base = bsb + (slot * 64 * ASTR + (wn * 32 + brow) * ASTR + bcolw) * 4u;

#pragma unroll
        for (int kg = 0; kg < 2; kg++) {
            unsigned a0[4], a1[4];
            ldm_x4(a0, a_base0 + kg * 32u);
            ldm_x4(a1, a_base1 + kg * 32u);
#pragma unroll
            for (int nb = 0; nb < 2; nb++) {
                unsigned b[4];
                ldm_x4(b, b_base + (unsigned)(nb * 16 * ASTR) * 4u + kg * 32u);
                mma16(acc[0][2 * nb], a0, b);
                mma16(acc[0][2 * nb + 1], a0, b + 2);
                mma16(acc[1][2 * nb], a1, b);
                mma16(acc[1][2 * nb + 1], a1, b + 2);
            }
        }
    }
}

// ---------------- QKV projection + RoPE ----------------
#define LOG2E 1.44269504088896340736f

__global__ void __launch_bounds__(256, 3) qkv_kernel() {
    extern __shared__ unsigned gsm[];

    const int z = blockIdx.z;
    const __half* Wt = (z == 0) ? g_Wqh : ((z == 1) ? g_Wkh : g_Wvh);

    const int tid = threadIdx.x;
    const int lane = tid & 31;
    const int warp = tid >> 5;
    const int wm = warp & 3;
    const int wn = warp >> 2;
    const int gid = lane >> 2;
    const int tig = lane & 3;
    const int s0 = blockIdx.y * 128;
    const int n0 = blockIdx.x * 64;
    const int head = blockIdx.x;
    const float qscale = (z == 0) ? 0.125f * LOG2E : 1.0f;

    float acc[2][4][4] = {};
    gemm_core_128x64(g_xh, Wt, s0, n0, acc, gsm);

#pragma unroll
    for (int ma = 0; ma < 2; ma++) {
#pragma unroll
        for (int na = 0; na < 4; na++) {
#pragma unroll
            for (int rr = 0; rr < 2; rr++) {
                int row = s0 + wm * 32 + ma * 16 + gid + rr * 8;
                int d = wn * 32 + na * 8 + 2 * tig;
                float v0 = acc[ma][na][2 * rr + 0];
                float v1 = acc[ma][na][2 * rr + 1];
                if (z < 2) {
                    float2 c = *(const float2*)&g_cos[row * HD + d];
                    float2 s = *(const float2*)&g_sin[row * HD + d];
                    float o0 = (v0 * c.x - v1 * s.x) * qscale;
                    float o1 = (v1 * c.y + v0 * s.y) * qscale;
                    __half* dst = (z == 0) ? g_Qh : g_Kh;
                    *(unsigned*)&dst[(size_t)head * SEQ * HD + (size_t)row * HD + d] =
                        packh2(o0, o1);
                } else {
                    size_t base = (size_t)head * SEQ * HD;
                    g_Vh[base + (size_t)d * SEQ + row] = __float2half_rn(v0);
                    g_Vh[base + (size_t)(d + 1) * SEQ + row] = __float2half_rn(v1);
                }
            }
        }
    }
}

// ---------------- output projection ----------------
__global__ void __launch_bounds__(256, 3) oproj_kernel(float* __restrict__ out) {
    extern __shared__ unsigned gsm[];

    const int tid = threadIdx.x;
    const int lane = tid & 31;
    const int warp = tid >> 5;
    const int wm = warp & 3;
    const int wn = warp >> 2;
    const int gid = lane >> 2;
    const int tig = lane & 3;
    const int s0 = blockIdx.y * 128;
    const int n0 = blockIdx.x * 64;

    float acc[2][4][4] = {};
    gemm_core_128x64(g_ctxh, g_Woh, s0, n0, acc, gsm);

#pragma unroll
    for (int ma = 0; ma < 2; ma++)
#pragma unroll
        for (int na = 0; na < 4; na++)
#pragma unroll
            for (int rr = 0; rr < 2; rr++) {
                int row = s0 + wm * 32 + ma * 16 + gid + rr * 8;
                int col = n0 + wn * 32 + na * 8 + 2 * tig;
                *(float2*)&out[(size_t)row * HDIM + col] =
                    make_float2(acc[ma][na][2 * rr + 0], acc[ma][na][2 * rr + 1]);
            }
}

// ---------------- flash attention: 3-stage ring, 1 sync/tile, voted max-skip ----------------
#define ATT_NI (SEQ / 64)
#define ATT_SMEM ((128 * WSTR + 3 * 64 * WSTR + 3 * 64 * WSTR) * 4 + 3 * 64 * 4)

__global__ void __launch_bounds__(256, 2) attn_kernel(const int* __restrict__ mask) {
    extern __shared__ unsigned sm_u[];
    unsigned* Qs = sm_u;                              // 128 x WSTR
    unsigned* Ks = Qs + 128 * WSTR;                   // 3 x 64 x WSTR
    unsigned* Vs = Ks + 3 * 64 * WSTR;                // 3 x 64 x WSTR
    int* smask = (int*)(Vs + 3 * 64 * WSTR);          // 3 x 64

    const int tid = threadIdx.x;
    const int lane = tid & 31;
    const int w = tid >> 5;
    const int gid = lane >> 2;
    const int tig = lane & 3;
    const int q0 = blockIdx.x * 128;
    const int h = blockIdx.y;
    const int qb = w * 16;

    const __half* Qg = g_Qh + (size_t)h * SEQ * HD;
    const __half* Kg = g_Kh + (size_t)h * SEQ * HD;
    const __half* Vg = g_Vh + (size_t)h * SEQ * HD;   // [d][s]

    unsigned qsb = (unsigned)__cvta_generic_to_shared(Qs);
    unsigned ksb = (unsigned)__cvta_generic_to_shared(Ks);
    unsigned vsb = (unsigned)__cvta_generic_to_shared(Vs);
    unsigned msb = (unsigned)__cvta_generic_to_shared(smask);

    const int arow = lane & 15;
    const int acolw = (lane >> 4) * 4;
    const int brow = ((lane & 16) ? 8 : 0) + (lane & 7);
    const int bcolw = ((lane >> 3) & 1) * 4;

    auto issue_kv = [&](int kt) {
        int k0 = kt * 64;
        unsigned slot = (unsigned)(kt % 3);
#pragma unroll
        for (int i = 0; i < 2; i++) {
            int f = tid + 256 * i;
            int row = f >> 3, ch = f & 7;
            cp16(ksb + (slot * 64 * WSTR + row * WSTR + ch * 4) * 4u,
                 &Kg[(size_t)(k0 + row) * HD + ch * 8]);
            cp16(vsb + (slot * 64 * WSTR + row * WSTR + ch * 4) * 4u,
                 &Vg[(size_t)row * SEQ + k0 + ch * 8]);
        }
        if (tid < 64) cp4(msb + (slot * 64 + tid) * 4u, &mask[k0 + tid]);
        CP_COMMIT();
    };

    // stage Q once
#pragma unroll
    for (int i = 0; i < 4; i++) {
        int f = tid + 256 * i;
        int row = f >> 3, ch = f & 7;
        *(uint4*)&Qs[row * WSTR + ch * 4] =
            *(const uint4*)&Qg[(size_t)(q0 + row) * HD + ch * 8];
    }

    float Oacc[8][4] = {};
    float mrow[2] = {-1e30f, -1e30f};
    float lrow[2] = {0.f, 0.f};

    issue_kv(0);
    issue_kv(1);

    const unsigned qaddr = qsb + (unsigned)((qb + arow) * WSTR + acolw) * 4u;

    for (int kt = 0; kt < ATT_NI; kt++) {
        if (kt == ATT_NI - 1) {
            asm volatile("cp.async.wait_group 0;");
        } else {
            asm volatile("cp.async.wait_group 1;");
        }
        __syncthreads();
        if (kt + 2 < ATT_NI) issue_kv(kt + 2);

        unsigned slot = (unsigned)(kt % 3);
        const unsigned kbase = ksb + (slot * 64 * WSTR + brow * WSTR + bcolw) * 4u;
        const unsigned vbase = vsb + (slot * 64 * WSTR + brow * WSTR + bcolw) * 4u;
        const int* Mf = smask + slot * 64;

        // ---- S = Q K^T ----
        float sacc[8][4] = {};
#pragma unroll
        for (int kg = 0; kg < 4; kg++) {
            unsigned a[4];
            ldm_x4(a, qaddr + kg * 32u);
#pragma unroll
            for (int nb = 0; nb < 4; nb++) {
                unsigned b[4];
                ldm_x4(b, kbase + (unsigned)(nb * 16 * WSTR) * 4u + kg * 32u);
                mma16(sacc[2 * nb], a, b);
                mma16(sacc[2 * nb + 1], a, b + 2);
            }
        }

        // ---- mask bias (skip when tile all-ones) ----
        bool localz = false;
        float bb[8][2];
#pragma unroll
        for (int na = 0; na < 8; na++) {
            int m0 = Mf[na * 8 + 2 * tig];
            int m1 = Mf[na * 8 + 2 * tig + 1];
            bb[na][0] = (m0 == 0) ? -1e30f : 0.f;
            bb[na][1] = (m1 == 0) ? -1e30f : 0.f;
            localz |= (m0 == 0) | (m1 == 0);
        }
        if (__any_sync(0xffffffffu, localz)) {
#pragma unroll
            for (int na = 0; na < 8; na++)
#pragma unroll
                for (int rr = 0; rr < 2; rr++) {
                    sacc[na][2 * rr + 0] += bb[na][0];
                    sacc[na][2 * rr + 1] += bb[na][1];
                }
        }

        // ---- online softmax (exp2 domain), voted skip of rescale ----
#pragma unroll
        for (int rr = 0; rr < 2; rr++) {
            float mt = -1e30f;
#pragma unroll
            for (int na = 0; na < 8; na++)
                mt = fmaxf(mt, fmaxf(sacc[na][2 * rr], sacc[na][2 * rr + 1]));
            mt = fmaxf(mt, __shfl_xor_sync(0xffffffffu, mt, 1));
            mt = fmaxf(mt, __shfl_xor_sync(0xffffffffu, mt, 2));
            if (__any_sync(0xffffffffu, mt > mrow[rr])) {
                float mnew = fmaxf(mrow[rr], mt);
                float corr = exp2f(mrow[rr] - mnew);
                lrow[rr] *= corr;
                mrow[rr] = mnew;
#pragma unroll
                for (int nd = 0; nd < 8; nd++) {
                    Oacc[nd][2 * rr + 0] *= corr;
                    Oacc[nd][2 * rr + 1] *= corr;
                }
            }
            float rs = 0.f;
#pragma unroll
            for (int na = 0; na < 8; na++) {
#pragma unroll
                for (int s = 0; s < 2; s++) {
                    float p = exp2f(sacc[na][2 * rr + s] - mrow[rr]);
                    sacc[na][2 * rr + s] = p;
                    rs += p;
                }
            }
            rs += __shfl_xor_sync(0xffffffffu, rs, 1);
            rs += __shfl_xor_sync(0xffffffffu, rs, 2);
            lrow[rr] += rs;
        }

        // ---- O += P V ----
#pragma unroll
        for (int kg = 0; kg < 4; kg++) {
            unsigned aP[4];
            aP[0] = packh2(sacc[2 * kg][0], sacc[2 * kg][1]);
            aP[1] = packh2(sacc[2 * kg][2], sacc[2 * kg][3]);
            aP[2] = packh2(sacc[2 * kg + 1][0], sacc[2 * kg + 1][1]);
            aP[3] = packh2(sacc[2 * kg + 1][2], sacc[2 * kg + 1][3]);
#pragma unroll
            for (int nb = 0; nb < 4; nb++) {
                unsigned b[4];
                ldm_x4(b, vbase + (unsigned)(nb * 16 * WSTR) * 4u + kg * 32u);
                mma16(Oacc[2 * nb], aP, b);
                mma16(Oacc[2 * nb + 1], aP, b + 2);
            }
        }
    }

    // epilogue: normalize, write ctx fp16
    float inv[2] = {1.0f / lrow[0], 1.0f / lrow[1]};
#pragma unroll
    for (int nd = 0; nd < 8; nd++)
#pragma unroll
        for (int rr = 0; rr < 2; rr++) {
            int row = q0 + qb + gid + rr * 8;
            int d = nd * 8 + 2 * tig;
            float iv = inv[rr];
            *(unsigned*)&g_ctxh[(size_t)row * HDIM + h * HD + d] =
                packh2(Oacc[nd][2 * rr] * iv, Oacc[nd][2 * rr + 1] * iv);
        }
}

// ---------------- launch ----------------
extern "C" void kernel_launch(void* const* d_in, const int* in_sizes, int n_in,
                              void* d_out, int out_size) {
    const float* x  = (const float*)d_in[0];
    const float* Wq = (const float*)d_in[1];
    const float* Wk = (const float*)d_in[2];
    const float* Wv = (const float*)d_in[3];
    const float* Wo = (const float*)d_in[4];
    const int* mask = (const int*)d_in[5];
    float* out = (float*)d_out;

    cudaFuncSetAttribute(qkv_kernel,
                         cudaFuncAttributeMaxDynamicSharedMemorySize, GEMM_SMEM);
    cudaFuncSetAttribute(oproj_kernel,
                         cudaFuncAttributeMaxDynamicSharedMemorySize, GEMM_SMEM);
    cudaFuncSetAttribute(attn_kernel,
                         cudaFuncAttributeMaxDynamicSharedMemorySize, ATT_SMEM);

    x2h_kernel<<<SEQ * HDIM / 4 / 256, 256>>>(x);
    wtrans_kernel<<<dim3(HDIM / 64, HDIM / 64, 4), 256>>>(Wq, Wk, Wv, Wo);
    rope_tables_kernel<<<(SEQ * HD + 255) / 256, 256>>>();
    qkv_kernel<<<dim3(NH, SEQ / 128, 3), 256, GEMM_SMEM>>>();
    attn_kernel<<<dim3(SEQ / 128, NH), 256, ATT_SMEM>>>(mask);
    oproj_kernel<<<dim3(HDIM / 64, SEQ / 128), 256, GEMM_SMEM>>>(out);
}